// round 10
// baseline (speedup 1.0000x reference)
#include <cuda_runtime.h>
#include <math.h>

#define GRID_N 256
#define KS 15
#define RAD 7

__device__ __forceinline__ unsigned redux_add_u32(unsigned v, unsigned mask) {
    unsigned r;
    asm volatile("redux.sync.add.u32 %0, %1, %2;" : "=r"(r) : "r"(v), "r"(mask));
    return r;
}

__global__ void __launch_bounds__(128)
latent_lookup_kernel(
    const float* __restrict__ q,        // [B,2]
    const float* __restrict__ temp,     // [1]
    const float* __restrict__ idx2d,    // [256,256,2]
    const float* __restrict__ rm2d,     // [256,256]
    const float* __restrict__ spacing,  // [2]
    int B,
    float* __restrict__ out)            // [2,B]
{
    const int gwarp = (int)((blockIdx.x * blockDim.x + threadIdx.x) >> 5);
    const int lane  = threadIdx.x & 31;
    if (gwarp >= B) return;

    // front-load scalars (independent loads)
    const float2 qv = __ldg(&((const float2*)q)[gwarp]);
    const float2 og = __ldg(&((const float2*)idx2d)[0]);
    const float2 sp = __ldg(&((const float2*)spacing)[0]);
    const float  tv = __ldg(&temp[0]);

    const float qx = qv.x, qy = qv.y;

    // rel_pos with exact rn division (must reproduce jnp rounding boundaries)
    const float rpx = (qx - og.x) / sp.x;
    const float rpy = (qy - og.y) / sp.y;
    int vx = (int)rintf(rpx);
    int vy = (int)rintf(rpy);
    vx = min(max(vx, RAD), GRID_N - 1 - RAD);   // never binds on valid data
    vy = min(max(vy, RAD), GRID_N - 1 - RAD);
    int fx = (int)floorf(rpx);                  // hard 2x2 cell corner
    int fy = (int)floorf(rpy);
    fx = min(max(fx, 0), GRID_N - 2);
    fy = min(max(fy, 0), GRID_N - 2);

    // ------------------------------------------------------------------
    // HARD: bit-exact fp32 sq_dist over the 2x2 cell corners (verified R6-R8)
    // ------------------------------------------------------------------
    const int  l3   = lane & 3;
    const bool isYc = (l3 >= 2);
    const int  cc   = isYc ? (fy + (l3 & 1)) : (fx + (l3 & 1));
    const float gvl = __ldg(&idx2d[isYc ? (2 * cc + 1) : (2 * GRID_N * cc)]);

    const float qn = __fadd_rn(__fmul_rn(qx, qx), __fmul_rn(qy, qy));
    const float ix = __shfl_sync(0xffffffffu, gvl, lane >> 1);        // gx[fx+i]
    const float iy = __shfl_sync(0xffffffffu, gvl, 2 + (lane & 1));   // gy[fy+j]
    unsigned key  = 0xFF800000u;  // mapped(+inf)
    int      flat = 0;
    {
        const float inn = __fadd_rn(__fmul_rn(ix, ix), __fmul_rn(iy, iy));
        const float dot = __fmaf_rn(qy, iy, __fmul_rn(qx, ix));
        const float dd  = __fsub_rn(__fadd_rn(qn, inn), __fmul_rn(2.0f, dot));
        const unsigned fb = __float_as_uint(dd);
        const unsigned k2 = fb ^ ((((int)fb) >> 31) | 0x80000000u);
        if (lane < 4) {
            key  = k2;
            flat = ((fx + (lane >> 1)) << 8) + (fy + (lane & 1));
        }
    }
    const unsigned mn   = __reduce_min_sync(0xffffffffu, key);
    const unsigned bal  = __ballot_sync(0xffffffffu, key == mn);
    const int  bestFlat = __shfl_sync(0xffffffffu, flat, __ffs(bal) - 1);
    const float hard = __ldg(&rm2d[bestFlat]);   // consumed only at final store

    // ------------------------------------------------------------------
    // SOFT: separable windowed softmax, row-pair mapping (R7 layout).
    //   ev: lanes 0..14 = ex, lane 15 = 0, lanes 16..30 = ey, lane 31 = 0
    //   lane column = lane&15; iteration r covers row 2r+isY.
    // ------------------------------------------------------------------
    const float invt = __fdividef(1.0f, tv + 1e-8f);
    const int   isY  = (lane >> 4) & 1;
    const int   hl   = lane & 15;
    float ev;
    {
        const int   c = (isY ? vy : vx) + hl - RAD;                  // in [0,255]
        const float n = isY ? (og.y + sp.y * (float)c) : (og.x + sp.x * (float)c);
        const float d = (isY ? qy : qx) - n;
        ev = (hl == 15) ? 0.0f : __expf(-(d * d) * invt);
    }
    // loop-invariant column weight (0 for phantom col 15 via ev[31])
    const float eyc = __shfl_sync(0xffffffffu, ev, 16 + hl);

    // batch the 8 row loads (full MLP)
    const float* rowp = rm2d + ((vx - RAD) << 8) + (vy - RAD) + min(hl, 14);
    float m[8];
    #pragma unroll
    for (int r = 0; r < 8; r++) {
        const int row = min(2 * r + isY, 14);    // folds away for r < 7
        m[r] = __ldg(rowp + (row << 8));
    }
    float ws = 0.0f;
    #pragma unroll
    for (int r = 0; r < 8; r++) {
        const float exr = __shfl_sync(0xffffffffu, ev, 2 * r + isY);
        ws = __fmaf_rn(exr, eyc * m[r], ws);
    }

    // ------------------------------------------------------------------
    // Reductions via fixed-point redux.sync.add.u32 (sm_103 has int redux only):
    //  ws   in [0,8]/lane, total <=225  -> scale 2^22 (max ~9.4e8 < 2^32)
    //  ev   in [0,1]/lane, half-sum <=15 -> scale 2^26 (max ~1e9  < 2^32)
    // Quantization error ~4e-8 relative: far under the 1e-3 gate.
    // Two disjoint converged 16-lane groups for the ev half-sums.
    // ------------------------------------------------------------------
    const unsigned hmask = isY ? 0xFFFF0000u : 0x0000FFFFu;
    const unsigned iev = __float2uint_rn(ev * 67108864.0f);          // 2^26
    const unsigned iws = __float2uint_rn(ws * 4194304.0f);           // 2^22
    const unsigned sred = redux_add_u32(iev, hmask);                 // sex | sey
    const unsigned sws  = redux_add_u32(iws, 0xffffffffu);
    const unsigned isey = __shfl_sync(0xffffffffu, sred, 16);

    if (lane == 0) {
        const float sex = (float)sred * 1.4901161193847656e-08f;     // 2^-26
        const float sey = (float)isey * 1.4901161193847656e-08f;
        const float wsf = (float)sws  * 2.3841857910156250e-07f;     // 2^-22
        out[gwarp]     = hard;                                       // row 0
        out[B + gwarp] = __fdividef(wsf, sex * sey);                 // row 1
    }
}

extern "C" void kernel_launch(void* const* d_in, const int* in_sizes, int n_in,
                              void* d_out, int out_size)
{
    const float* q       = (const float*)d_in[0];
    const float* temp    = (const float*)d_in[1];
    // d_in[2] indices_db, d_in[3] relevant_metrics: unused
    const float* idx2d   = (const float*)d_in[4];
    const float* rm2d    = (const float*)d_in[5];
    const float* spacing = (const float*)d_in[6];

    const int B = in_sizes[0] / 2;
    const int threads = 128;
    const int blocks  = (B * 32 + threads - 1) / threads;
    latent_lookup_kernel<<<blocks, threads>>>(q, temp, idx2d, rm2d, spacing, B, (float*)d_out);
}

// round 11
// speedup vs baseline: 1.0386x; 1.0386x over previous
#include <cuda_runtime.h>
#include <math.h>

#define GRID_N 256
#define KS 15
#define RAD 7

__global__ void __launch_bounds__(128, 4)
latent_lookup_kernel(
    const float* __restrict__ q,        // [B,2]
    const float* __restrict__ temp,     // [1]
    const float* __restrict__ idx2d,    // [256,256,2]
    const float* __restrict__ rm2d,     // [256,256]
    const float* __restrict__ spacing,  // [2]
    int B,
    float* __restrict__ out)            // [2,B]
{
    const int gwarp = (int)((blockIdx.x * blockDim.x + threadIdx.x) >> 5);
    const int lane  = threadIdx.x & 31;
    const int nPair = B >> 1;
    if (gwarp >= nPair) return;

    // ---- phase 1: all independent scalar loads up front ----
    const float2 qA = __ldg(&((const float2*)q)[2 * gwarp + 0]);
    const float2 qB = __ldg(&((const float2*)q)[2 * gwarp + 1]);
    const float2 og = __ldg(&((const float2*)idx2d)[0]);
    const float2 sp = __ldg(&((const float2*)spacing)[0]);
    const float  tv = __ldg(&temp[0]);

    // ---- phase 2: voxel/cell indices, A/B interleaved (exact rn div + rintf) ----
    const float rpxA = (qA.x - og.x) / sp.x;
    const float rpxB = (qB.x - og.x) / sp.x;
    const float rpyA = (qA.y - og.y) / sp.y;
    const float rpyB = (qB.y - og.y) / sp.y;
    const int vxA = min(max((int)rintf(rpxA), RAD), GRID_N - 1 - RAD);
    const int vxB = min(max((int)rintf(rpxB), RAD), GRID_N - 1 - RAD);
    const int vyA = min(max((int)rintf(rpyA), RAD), GRID_N - 1 - RAD);
    const int vyB = min(max((int)rintf(rpyB), RAD), GRID_N - 1 - RAD);
    const int fxA = min(max((int)floorf(rpxA), 0), GRID_N - 2);
    const int fxB = min(max((int)floorf(rpxB), 0), GRID_N - 2);
    const int fyA = min(max((int)floorf(rpyA), 0), GRID_N - 2);
    const int fyB = min(max((int)floorf(rpyB), 0), GRID_N - 2);

    // ---- phase 3: issue BOTH soft m-load batches NOW (longest latency first;
    //      the hard path below executes in their shadow) ----
    const int isY = (lane >> 4) & 1;
    const int hl  = lane & 15;
    const float* rowA = rm2d + ((vxA - RAD) << 8) + (vyA - RAD) + min(hl, 14);
    const float* rowB = rm2d + ((vxB - RAD) << 8) + (vyB - RAD) + min(hl, 14);
    float mA[8], mB[8];
    #pragma unroll
    for (int r = 0; r < 8; r++) {
        const int row = min(2 * r + isY, 14);
        mA[r] = __ldg(rowA + (row << 8));
        mB[r] = __ldg(rowB + (row << 8));
    }

    // ---- phase 4: HARD x2, bit-exact fp32 sq_dist over 2x2 corners (verified R6-R10) ----
    const int  l3   = lane & 3;
    const bool isYc = (l3 >= 2);
    const int  ccA  = isYc ? (fyA + (l3 & 1)) : (fxA + (l3 & 1));
    const int  ccB  = isYc ? (fyB + (l3 & 1)) : (fxB + (l3 & 1));
    const float gvA = __ldg(&idx2d[isYc ? (2 * ccA + 1) : (2 * GRID_N * ccA)]);
    const float gvB = __ldg(&idx2d[isYc ? (2 * ccB + 1) : (2 * GRID_N * ccB)]);

    const float qnA = __fadd_rn(__fmul_rn(qA.x, qA.x), __fmul_rn(qA.y, qA.y));
    const float qnB = __fadd_rn(__fmul_rn(qB.x, qB.x), __fmul_rn(qB.y, qB.y));
    const float ixA = __shfl_sync(0xffffffffu, gvA, lane >> 1);
    const float ixB = __shfl_sync(0xffffffffu, gvB, lane >> 1);
    const float iyA = __shfl_sync(0xffffffffu, gvA, 2 + (lane & 1));
    const float iyB = __shfl_sync(0xffffffffu, gvB, 2 + (lane & 1));

    unsigned keyA = 0xFF800000u, keyB = 0xFF800000u;
    int flatA = 0, flatB = 0;
    {
        const float innA = __fadd_rn(__fmul_rn(ixA, ixA), __fmul_rn(iyA, iyA));
        const float innB = __fadd_rn(__fmul_rn(ixB, ixB), __fmul_rn(iyB, iyB));
        const float dotA = __fmaf_rn(qA.y, iyA, __fmul_rn(qA.x, ixA));
        const float dotB = __fmaf_rn(qB.y, iyB, __fmul_rn(qB.x, ixB));
        const float ddA  = __fsub_rn(__fadd_rn(qnA, innA), __fmul_rn(2.0f, dotA));
        const float ddB  = __fsub_rn(__fadd_rn(qnB, innB), __fmul_rn(2.0f, dotB));
        const unsigned fbA = __float_as_uint(ddA);
        const unsigned fbB = __float_as_uint(ddB);
        const unsigned kA  = fbA ^ ((((int)fbA) >> 31) | 0x80000000u);
        const unsigned kB  = fbB ^ ((((int)fbB) >> 31) | 0x80000000u);
        if (lane < 4) {
            keyA = kA; flatA = ((fxA + (lane >> 1)) << 8) + (fyA + (lane & 1));
            keyB = kB; flatB = ((fxB + (lane >> 1)) << 8) + (fyB + (lane & 1));
        }
    }
    const unsigned mnA  = __reduce_min_sync(0xffffffffu, keyA);
    const unsigned mnB  = __reduce_min_sync(0xffffffffu, keyB);
    const unsigned balA = __ballot_sync(0xffffffffu, keyA == mnA);
    const unsigned balB = __ballot_sync(0xffffffffu, keyB == mnB);
    const int bfA = __shfl_sync(0xffffffffu, flatA, __ffs(balA) - 1);
    const int bfB = __shfl_sync(0xffffffffu, flatB, __ffs(balB) - 1);
    const float hardA = __ldg(&rm2d[bfA]);   // consumed only at final store
    const float hardB = __ldg(&rm2d[bfB]);

    // ---- phase 5: SOFT x2 exp weights (R7 row-pair layout) ----
    const float invt = __fdividef(1.0f, tv + 1e-8f);
    float evA, evB;
    {
        const int   cA = (isY ? vyA : vxA) + hl - RAD;
        const int   cB = (isY ? vyB : vxB) + hl - RAD;
        const float nA = isY ? (og.y + sp.y * (float)cA) : (og.x + sp.x * (float)cA);
        const float nB = isY ? (og.y + sp.y * (float)cB) : (og.x + sp.x * (float)cB);
        const float dA = (isY ? qA.y : qA.x) - nA;
        const float dB = (isY ? qB.y : qB.x) - nB;
        evA = (hl == 15) ? 0.0f : __expf(-(dA * dA) * invt);
        evB = (hl == 15) ? 0.0f : __expf(-(dB * dB) * invt);
    }
    const float eycA = __shfl_sync(0xffffffffu, evA, 16 + hl);
    const float eycB = __shfl_sync(0xffffffffu, evB, 16 + hl);

    float wsA = 0.0f, wsB = 0.0f;
    #pragma unroll
    for (int r = 0; r < 8; r++) {
        const float exA = __shfl_sync(0xffffffffu, evA, 2 * r + isY);
        const float exB = __shfl_sync(0xffffffffu, evB, 2 * r + isY);
        wsA = __fmaf_rn(exA, eycA * mA[r], wsA);
        wsB = __fmaf_rn(exB, eycB * mB[r], wsB);
    }

    // ---- phase 6: reductions, A/B interleaved (pipelined shfl rounds) ----
    float redA = evA, redB = evB;
    #pragma unroll
    for (int off = 8; off; off >>= 1) {
        redA += __shfl_xor_sync(0xffffffffu, redA, off);
        redB += __shfl_xor_sync(0xffffffffu, redB, off);
    }
    #pragma unroll
    for (int off = 16; off; off >>= 1) {
        wsA += __shfl_xor_sync(0xffffffffu, wsA, off);
        wsB += __shfl_xor_sync(0xffffffffu, wsB, off);
    }
    const float seyA = __shfl_sync(0xffffffffu, redA, 16);
    const float seyB = __shfl_sync(0xffffffffu, redB, 16);

    if (lane == 0) {
        ((float2*)out)[gwarp] = make_float2(hardA, hardB);           // row 0 pair
        ((float2*)(out + B))[gwarp] =
            make_float2(__fdividef(wsA, redA * seyA),
                        __fdividef(wsB, redB * seyB));               // row 1 pair
    }
}

extern "C" void kernel_launch(void* const* d_in, const int* in_sizes, int n_in,
                              void* d_out, int out_size)
{
    const float* q       = (const float*)d_in[0];
    const float* temp    = (const float*)d_in[1];
    // d_in[2] indices_db, d_in[3] relevant_metrics: unused
    const float* idx2d   = (const float*)d_in[4];
    const float* rm2d    = (const float*)d_in[5];
    const float* spacing = (const float*)d_in[6];

    const int B = in_sizes[0] / 2;
    const int nPair   = B / 2;                   // 2 queries per warp
    const int threads = 128;
    const int blocks  = (nPair * 32 + threads - 1) / threads;
    latent_lookup_kernel<<<blocks, threads>>>(q, temp, idx2d, rm2d, spacing, B, (float*)d_out);
}